// round 1
// baseline (speedup 1.0000x reference)
#include <cuda_runtime.h>
#include <cuda_bf16.h>
#include <cstdint>

// MissHitScatter: inputs [N=65536, D=1024] f32 -> out [P=4, N, D] f32.
// IS_HIT=true => path 0 gets the input verbatim, paths 1..3 are all zeros.
// Pure memory-movement problem: 256 MiB copy + 768 MiB zero-fill.
//
// Strategy: memset the zero region (single pass, peak write BW) and a D2D
// memcpy for slice 0. Both are valid CUDA-graph node types under stream
// capture on the legacy default stream (which the harness captures).

extern "C" void kernel_launch(void* const* d_in, const int* in_sizes, int n_in,
                              void* d_out, int out_size) {
    const int n_elems = in_sizes[0];                 // 65536 * 1024
    const size_t slice_bytes = (size_t)n_elems * sizeof(float);

    char* out = (char*)d_out;

    // Paths 1..3: zeros (768 MiB)
    cudaMemsetAsync(out + slice_bytes, 0, 3 * slice_bytes, 0);

    // Path 0: copy of input (256 MiB read + 256 MiB write)
    cudaMemcpyAsync(out, d_in[0], slice_bytes, cudaMemcpyDeviceToDevice, 0);
}

// round 2
// speedup vs baseline: 1.3728x; 1.3728x over previous
#include <cuda_runtime.h>
#include <cuda_bf16.h>
#include <cstdint>

// MissHitScatter: inputs [N=65536, D=1024] f32 -> out [P=4, N, D] f32.
// IS_HIT=true => slice 0 = input copy, slices 1..3 = zeros.
//
// Single fused kernel: one pass over the whole 1 GiB output.
//   - global float4 index i in [0, 4*n4)
//   - i <  n4  : out[i] = in[i]   (copy, 16B load + 16B store)
//   - i >= n4  : out[i] = 0       (pure 16B store)
// One launch => copy and fill overlap, DRAM stays saturated end to end.

__global__ void misshit_scatter_kernel(const float4* __restrict__ in,
                                       float4* __restrict__ out,
                                       size_t n4) {
    size_t i = (size_t)blockIdx.x * blockDim.x + threadIdx.x;
    size_t total = n4 * 4;
    if (i >= total) return;

    float4 v = make_float4(0.f, 0.f, 0.f, 0.f);
    if (i < n4) {
        v = __ldg(in + i);
    }
    out[i] = v;
}

extern "C" void kernel_launch(void* const* d_in, const int* in_sizes, int n_in,
                              void* d_out, int out_size) {
    const size_t n_elems = (size_t)in_sizes[0];       // 65536 * 1024 floats
    const size_t n4 = n_elems / 4;                    // float4 per slice
    const size_t total4 = n4 * 4;                     // float4 in full output

    const int threads = 256;
    const int blocks = (int)((total4 + threads - 1) / threads);

    misshit_scatter_kernel<<<blocks, threads>>>(
        (const float4*)d_in[0], (float4*)d_out, n4);
}